// round 13
// baseline (speedup 1.0000x reference)
#include <cuda_runtime.h>
#include <cstdint>

#define T_STEPS 2048
#define BATCH   1024
#define INPUT   4
#define HID     10
#define OUTF    4
#define CHUNK   16          // timesteps staged per warp per cp.async chunk
#define BPB     8           // batches per block = warps per block (1 batch/warp)
#define THREADS 256         // 8 warps -> 128 blocks, 2 warps per SMSP

typedef unsigned long long u64;

// 84MB scratch for h history (module-static: no runtime allocation)
__device__ float g_hhist[(size_t)T_STEPS * BATCH * HID];

// ---- Blackwell packed f32x2 helpers ----
__device__ __forceinline__ u64 pk2(float lo, float hi) {
    u64 r; asm("mov.b64 %0, {%1,%2};" : "=l"(r) : "f"(lo), "f"(hi)); return r;
}
__device__ __forceinline__ void up2(u64 v, float& lo, float& hi) {
    asm("mov.b64 {%0,%1}, %2;" : "=f"(lo), "=f"(hi) : "l"(v));
}
__device__ __forceinline__ u64 ffma2(u64 a, u64 b, u64 c) {
    u64 d; asm("fma.rn.f32x2 %0, %1, %2, %3;" : "=l"(d) : "l"(a), "l"(b), "l"(c)); return d;
}
__device__ __forceinline__ u64 fadd2(u64 a, u64 b) {
    u64 d; asm("add.rn.f32x2 %0, %1, %2;" : "=l"(d) : "l"(a), "l"(b)); return d;
}
__device__ __forceinline__ u64 fmul2(u64 a, u64 b) {
    u64 d; asm("mul.rn.f32x2 %0, %1, %2;" : "=l"(d) : "l"(a), "l"(b)); return d;
}

// HW tanh (MUFU)
__device__ __forceinline__ float htanh(float x) {
    float y; asm("tanh.approx.f32 %0, %1;" : "=f"(y) : "f"(x)); return y;
}

__device__ __forceinline__ void cp_async16(void* dst, const void* src) {
    unsigned d = (unsigned)__cvta_generic_to_shared(dst);
    asm volatile("cp.async.ca.shared.global [%0], [%1], 16;\n" :: "r"(d), "l"(src));
}
__device__ __forceinline__ void cp_commit() {
    asm volatile("cp.async.commit_group;\n" ::: "memory");
}
__device__ __forceinline__ void cp_wait1() {
    asm volatile("cp.async.wait_group 1;\n" ::: "memory");
}

// ============================================================================
// Phase 1: recurrence. One batch per warp, warp-autonomous (no block sync in
// the loop). Lanes 0-9 own gate pair (i,g); lanes 16-25 own (f,o); the f/o
// sigmoids cross the 16-lane boundary via 2 shfl_xor. h is broadcast through
// a per-warp smem buffer storing duplicated {h,h} pairs, reloaded as LDS.128.
// FC deferred to phase 2 via g_hhist.
// ============================================================================
__global__ void __launch_bounds__(THREADS, 1)
lstm_recurrence_kernel(const float* __restrict__ x,
                       const float* __restrict__ h0,
                       const float* __restrict__ c0,
                       const float* __restrict__ W_ih,
                       const float* __restrict__ W_hh,
                       const float* __restrict__ b_ih,
                       const float* __restrict__ b_hh,
                       float* __restrict__ out,
                       int write_state)
{
    // per-warp private double-buffered x stage + h broadcast buffer
    __shared__ float4 sx[BPB][2][CHUNK];
    __shared__ __align__(16) float2 hbuf[BPB][12];   // 96B stride, 16B-aligned

    const int tid  = threadIdx.x;
    const int warp = tid >> 5;
    const int lane = tid & 31;
    const int role = (lane >> 4) & 1;          // 0: (i,g) rows, 1: (f,o) rows
    const int jj   = lane & 15;
    const int j    = (jj < HID) ? jj : (HID - 1);

    const int batch = blockIdx.x * BPB + warp;

    // rows: role0 -> (i=j, g=2H+j); role1 -> (f=H+j, o=3H+j)
    const int r_lo = role ? (HID + j)     : j;
    const int r_hi = role ? (3 * HID + j) : (2 * HID + j);
    // prescale sigmoid gates (i,f,o) by 0.5 so sigmoid = 0.5*tanh(acc)+0.5
    const float s_lo = 0.5f;                   // i or f: always sigmoid
    const float s_hi = role ? 0.5f : 1.0f;     // o: sigmoid ; g: tanh

    u64 wih[INPUT], whh[HID], bias2;
#pragma unroll
    for (int k = 0; k < INPUT; k++)
        wih[k] = pk2(W_ih[r_lo * INPUT + k] * s_lo, W_ih[r_hi * INPUT + k] * s_hi);
#pragma unroll
    for (int k = 0; k < HID; k++)
        whh[k] = pk2(W_hh[r_lo * HID + k] * s_lo, W_hh[r_hi * HID + k] * s_hi);
    bias2 = pk2((b_ih[r_lo] + b_hh[r_lo]) * s_lo, (b_ih[r_hi] + b_hh[r_hi]) * s_hi);

    // state: h duplicated {h,h}; c scalar (meaningful on lanes 0-9)
    u64 hd[HID];
#pragma unroll
    for (int k = 0; k < HID; k++) {
        const float hv = h0[batch * HID + k];
        hd[k] = pk2(hv, hv);
    }
    float c = c0[batch * HID + j];
    float hlast = 0.0f;

    const float4* x4 = reinterpret_cast<const float4*>(x);

    // prefetch chunk 0: lanes 0-15 fetch one timestep each (this warp's batch)
    if (lane < CHUNK)
        cp_async16(&sx[warp][0][lane], x4 + (size_t)lane * BATCH + batch);
    cp_commit();

    const unsigned hb = (unsigned)__cvta_generic_to_shared(&hbuf[warp][0]);

    const int NCH = T_STEPS / CHUNK;   // 128
    for (int ch = 0; ch < NCH; ch++) {
        if (ch + 1 < NCH && lane < CHUNK) {
            cp_async16(&sx[warp][(ch + 1) & 1][lane],
                       x4 + (size_t)((ch + 1) * CHUNK + lane) * BATCH + batch);
        }
        cp_commit();
        cp_wait1();          // this warp's chunk `ch` resident
        __syncwarp();        // make async-copied data visible warp-wide

        const int buf = ch & 1;
#pragma unroll 4
        for (int s = 0; s < CHUNK; s++) {
            const float4 xv = sx[warp][buf][s];   // warp-uniform broadcast
            const u64 xd0 = pk2(xv.x, xv.x);
            const u64 xd1 = pk2(xv.y, xv.y);
            const u64 xd2 = pk2(xv.z, xv.z);
            const u64 xd3 = pk2(xv.w, xv.w);

            // x-part (independent of h)
            u64 xc  = ffma2(xd0, wih[0], bias2);
            u64 xc2 = fmul2(xd1, wih[1]);
            xc  = ffma2(xd2, wih[2], xc);
            xc2 = ffma2(xd3, wih[3], xc2);

            // h-part: 4 short accumulator chains + tree combine
            u64 a  = ffma2(hd[0], whh[0], xc);
            u64 b  = ffma2(hd[1], whh[1], xc2);
            u64 cc = fmul2(hd[2], whh[2]);
            u64 dd = fmul2(hd[3], whh[3]);
            a  = ffma2(hd[4], whh[4], a);
            b  = ffma2(hd[5], whh[5], b);
            cc = ffma2(hd[6], whh[6], cc);
            dd = ffma2(hd[7], whh[7], dd);
            a  = ffma2(hd[8], whh[8], a);
            b  = ffma2(hd[9], whh[9], b);
            float zlo, zhi;
            up2(fadd2(fadd2(a, cc), fadd2(b, dd)), zlo, zhi);

            const float tlo = htanh(zlo);   // role0: tanh(i/2) ; role1: tanh(f/2)
            const float thi = htanh(zhi);   // role0: tanh(g)   ; role1: tanh(o/2)

            // local products, then exchange f/o across the 16-lane boundary
            const float sg_lo = fmaf(0.5f, tlo, 0.5f);  // role0: sigma(i); role1: sigma(f)
            const float sg_hi = fmaf(0.5f, thi, 0.5f);  // role1: sigma(o) (role0: unused)
            const float p     = sg_lo * thi;            // role0: sigma(i)*tanh(g)

            const float vA = role ? sg_lo : p;     // exchange payloads
            const float vB = sg_hi;
            const float fg = __shfl_xor_sync(0xffffffffu, vA, 16);  // role0 gets sigma(f)
            const float og = __shfl_xor_sync(0xffffffffu, vB, 16);  // role0 gets sigma(o)

            // c/h update (meaningful on lanes 0-9)
            c = fmaf(fg, c, p);
            const float hn = og * htanh(c);
            hlast = hn;

            // broadcast: lanes 0-9 store duplicated pair, all lanes reload
            if (lane < HID) {
                const float2 hv2 = make_float2(hn, hn);
                asm volatile("st.shared.v2.f32 [%0], {%1,%2};"
                             :: "r"(hb + lane * 8), "f"(hv2.x), "f"(hv2.y));
                const int t = ch * CHUNK + s;
                g_hhist[((size_t)t * BATCH + batch) * HID + lane] = hn;
            }
            __syncwarp();
#pragma unroll
            for (int k = 0; k < HID; k += 2) {
                asm volatile("ld.shared.v4.b32 {%0,%1,%2,%3}, [%4];"
                             : "=r"(((unsigned*)&hd[k])[0]), "=r"(((unsigned*)&hd[k])[1]),
                               "=r"(((unsigned*)&hd[k+1])[0]), "=r"(((unsigned*)&hd[k+1])[1])
                             : "r"(hb + k * 8));
            }
        }
    }

    // final states (hT, cT) appended after `out` in the flattened pytree
    if (write_state && lane < HID) {
        const size_t off = (size_t)T_STEPS * BATCH * OUTF;
        out[off + (size_t)batch * HID + lane] = hlast;
        out[off + (size_t)BATCH * HID + (size_t)batch * HID + lane] = c;
    }
}

// ============================================================================
// Phase 2: out[t*B+b, :] = h[t,b,:] @ W_fc^T + b_fc   (embarrassingly parallel)
// ============================================================================
__global__ void __launch_bounds__(256)
lstm_fc_kernel(const float* __restrict__ W_fc,
               const float* __restrict__ b_fc,
               float* __restrict__ out)
{
    __shared__ float wf[OUTF * HID];
    __shared__ float bf[OUTF];
    if (threadIdx.x < OUTF * HID) wf[threadIdx.x] = W_fc[threadIdx.x];
    if (threadIdx.x < OUTF)       bf[threadIdx.x] = b_fc[threadIdx.x];
    __syncthreads();

    const size_t idx = (size_t)blockIdx.x * blockDim.x + threadIdx.x;  // (t,b) pair
    if (idx >= (size_t)T_STEPS * BATCH) return;

    const float* h = &g_hhist[idx * HID];
    float hv[HID];
    const float2* h2 = reinterpret_cast<const float2*>(h);   // 40B rows -> 8B aligned
#pragma unroll
    for (int k = 0; k < HID / 2; k++) {
        const float2 v = h2[k];
        hv[2 * k] = v.x; hv[2 * k + 1] = v.y;
    }

    float4 r;
    float* rp = reinterpret_cast<float*>(&r);
#pragma unroll
    for (int o = 0; o < OUTF; o++) {
        float acc0 = bf[o], acc1 = 0.0f;
#pragma unroll
        for (int k = 0; k < HID; k += 2) {
            acc0 = fmaf(hv[k],     wf[o * HID + k],     acc0);
            acc1 = fmaf(hv[k + 1], wf[o * HID + k + 1], acc1);
        }
        rp[o] = acc0 + acc1;
    }
    reinterpret_cast<float4*>(out)[idx] = r;
}

extern "C" void kernel_launch(void* const* d_in, const int* in_sizes, int n_in,
                              void* d_out, int out_size) {
    const float* x    = (const float*)d_in[0];
    const float* h0   = (const float*)d_in[1];
    const float* c0   = (const float*)d_in[2];
    const float* W_ih = (const float*)d_in[3];
    const float* W_hh = (const float*)d_in[4];
    const float* b_ih = (const float*)d_in[5];
    const float* b_hh = (const float*)d_in[6];
    const float* W_fc = (const float*)d_in[7];
    const float* b_fc = (const float*)d_in[8];
    float* out = (float*)d_out;

    const long long need_state = (long long)T_STEPS * BATCH * OUTF + 2LL * BATCH * HID;
    const int write_state = (out_size >= need_state) ? 1 : 0;

    lstm_recurrence_kernel<<<BATCH / BPB, THREADS>>>(
        x, h0, c0, W_ih, W_hh, b_ih, b_hh, out, write_state);

    const long long nrows = (long long)T_STEPS * BATCH;
    lstm_fc_kernel<<<(int)((nrows + 255) / 256), 256>>>(W_fc, b_fc, out);
}